// round 9
// baseline (speedup 1.0000x reference)
#include <cuda_runtime.h>
#include <cstdint>

#define RL   132
#define NTH  256
#define NHID 6

// float offsets in dynamic smem
#define F_ADJ  0                 // 128*132 adj row-major (A of GEMM2)
#define F_ACT  16896             // 128*132 X / Y^T / X' multiplexed
#define F_WT   33792             // 128*132 W^T[u][c] (B of GEMM1)
#define F_X0   50688             // 128*16 input features (A of input GEMM)
#define F_WINT 52736             // 128*24 W_in^T (B of input GEMM)
#define F_BIN  55808             // 128
#define F_BIA  55936             // 768
#define F_MSK  56704             // 128
#define F_WO   56832             // 128
#define F_PART 56960             // 512 (only 256 used)
#define F_RED  57472             // 8 (RED[7] = denom)
#define F_BOUT 57480
#define SMEM_FLOATS 57488
#define SMEM_BYTES  (SMEM_FLOATS * 4)

__device__ __forceinline__ uint32_t smem_u32(const void* p) {
    uint32_t a;
    asm("{ .reg .u64 t; cvta.to.shared.u64 t, %1; cvt.u32.u64 %0, t; }" : "=r"(a) : "l"(p));
    return a;
}

__device__ __forceinline__ float tf32r(float x) {
    float y;
    asm("cvt.rna.tf32.f32 %0, %1;" : "=f"(y) : "f"(x));
    return y;
}

__device__ __forceinline__ void ldsm4(uint32_t addr, uint32_t& r0, uint32_t& r1,
                                      uint32_t& r2, uint32_t& r3) {
    asm volatile("ldmatrix.sync.aligned.m8n8.x4.shared.b16 {%0,%1,%2,%3}, [%4];"
                 : "=r"(r0), "=r"(r1), "=r"(r2), "=r"(r3) : "r"(addr));
}

__device__ __forceinline__ void mma8(float* d,
                                     uint32_t a0, uint32_t a1, uint32_t a2, uint32_t a3,
                                     uint32_t b0, uint32_t b1) {
    asm volatile("mma.sync.aligned.m16n8k8.row.col.f32.tf32.tf32.f32 "
                 "{%0,%1,%2,%3}, {%4,%5,%6,%7}, {%8,%9}, {%0,%1,%2,%3};"
                 : "+f"(d[0]), "+f"(d[1]), "+f"(d[2]), "+f"(d[3])
                 : "r"(a0), "r"(a1), "r"(a2), "r"(a3), "r"(b0), "r"(b1));
}

__device__ __forceinline__ void zero_acc(float (&acc)[4][4][4]) {
#pragma unroll
    for (int i = 0; i < 4; ++i)
#pragma unroll
        for (int j = 0; j < 4; ++j)
#pragma unroll
            for (int q = 0; q < 4; ++q) acc[i][j][q] = 0.0f;
}

// 128x128x128 GEMM, 8 warps, 64x32 warp tiles.
// A row-major [m][k] stride RL at aA (warp's m-base + fragOff already applied),
// B^T row-major [n][k] stride RL at aB. Explicit k double-buffer pipeline.
// PREF: stage W[l+1]^T (global row-major [c][u]) into F_WT, spread over k-steps.
template<bool PREF>
__device__ __forceinline__ void gemm128(uint32_t aA, uint32_t aB,
                                        float (&acc)[4][4][4],
                                        const float* __restrict__ wg,
                                        float* __restrict__ smf,
                                        int warp, int lane) {
    const uint32_t MSTEP = 16u * RL * 4u;
    uint32_t A[2][4][4];
    uint32_t B[2][2][4];
    float4 ring[4];
    int cbase = 0, ubase = 0;
    if (PREF) {
        cbase = lane & 7;                       // c = 8k + cbase
        ubase = warp * 16 + ((lane >> 3) << 2); // u0 (4 consecutive u per lane)
#pragma unroll
        for (int r = 0; r < 4; ++r)
            ring[r] = *(const float4*)(wg + (8 * r + cbase) * 128 + ubase);
    }
    // k = 0 fragments
#pragma unroll
    for (int mt = 0; mt < 4; ++mt)
        ldsm4(aA + mt * MSTEP, A[0][mt][0], A[0][mt][1], A[0][mt][2], A[0][mt][3]);
#pragma unroll
    for (int nb = 0; nb < 2; ++nb)
        ldsm4(aB + nb * MSTEP, B[0][nb][0], B[0][nb][1], B[0][nb][2], B[0][nb][3]);

#pragma unroll
    for (int k = 0; k < 16; ++k) {
        const int cur = k & 1, nxt = cur ^ 1;
        if (k < 15) {
#pragma unroll
            for (int mt = 0; mt < 4; ++mt)
                ldsm4(aA + mt * MSTEP + (uint32_t)(k + 1) * 32u,
                      A[nxt][mt][0], A[nxt][mt][1], A[nxt][mt][2], A[nxt][mt][3]);
#pragma unroll
            for (int nb = 0; nb < 2; ++nb)
                ldsm4(aB + nb * MSTEP + (uint32_t)(k + 1) * 32u,
                      B[nxt][nb][0], B[nxt][nb][1], B[nxt][nb][2], B[nxt][nb][3]);
        }
#pragma unroll
        for (int mt = 0; mt < 4; ++mt)
#pragma unroll
            for (int nt = 0; nt < 4; ++nt)
                mma8(acc[mt][nt],
                     A[cur][mt][0], A[cur][mt][1], A[cur][mt][2], A[cur][mt][3],
                     B[cur][nt >> 1][nt & 1], B[cur][nt >> 1][(nt & 1) + 2]);
        if (PREF && k >= 1) {
            const int kk = k - 1;
            const int c = 8 * kk + cbase;
            float4 v = ring[kk & 3];
            smf[F_WT + (ubase + 0) * RL + c] = tf32r(v.x);
            smf[F_WT + (ubase + 1) * RL + c] = tf32r(v.y);
            smf[F_WT + (ubase + 2) * RL + c] = tf32r(v.z);
            smf[F_WT + (ubase + 3) * RL + c] = tf32r(v.w);
            if (kk + 4 < 16)
                ring[kk & 3] = *(const float4*)(wg + (8 * (kk + 4) + cbase) * 128 + ubase);
        }
    }
    if (PREF) {
        const int c = 8 * 15 + cbase;
        float4 v = ring[15 & 3];
        smf[F_WT + (ubase + 0) * RL + c] = tf32r(v.x);
        smf[F_WT + (ubase + 1) * RL + c] = tf32r(v.y);
        smf[F_WT + (ubase + 2) * RL + c] = tf32r(v.z);
        smf[F_WT + (ubase + 3) * RL + c] = tf32r(v.w);
    }
}

__global__ __launch_bounds__(NTH, 1)
void gcn_mma_kernel(const int* __restrict__ pdg,
                    const float* __restrict__ feat,
                    const float* __restrict__ adj,
                    const float* __restrict__ mask,
                    const float* __restrict__ emb,
                    const float* __restrict__ W_in,
                    const float* __restrict__ b_in,
                    const float* __restrict__ W_h,
                    const float* __restrict__ b_h,
                    const float* __restrict__ W_out,
                    const float* __restrict__ b_out,
                    float* __restrict__ out)
{
    extern __shared__ float smf[];
    const uint32_t SB = smem_u32(smf);

    const int b    = blockIdx.x;
    const int tid  = threadIdx.x;
    const int lane = tid & 31;
    const int warp = tid >> 5;          // 0..7

    // 8 warps: 2 (m) x 4 (n), warp tile 64x32
    const int m0 = (warp >> 2) * 64;
    const int n0 = (warp & 3) * 32;

    // ldmatrix per-thread segment pattern
    const int aRow   = (lane & 7) + ((lane >> 3) & 1) * 8;
    const int aCol16 = lane >> 4;
    const uint32_t fragOff = (uint32_t)(aRow * RL) * 4 + (uint32_t)aCol16 * 16;

    // epilogue pattern
    const int er = lane >> 2;
    const int ec = (lane & 3) * 2;

    const float* adjb = adj + (size_t)b * 16384;

    // ================= staging =================
#pragma unroll
    for (int i = 0; i < 16; ++i) {             // adj -> ADJ (cvt)
        int idx = i * 256 + tid;
        int row = idx >> 5, c4 = idx & 31;
        float4 v = *(const float4*)(adjb + row * 128 + c4 * 4);
        float4 w = make_float4(tf32r(v.x), tf32r(v.y), tf32r(v.z), tf32r(v.w));
        *(float4*)&smf[F_ACT + row * RL + c4 * 4] = w;  // temp: reuse pattern below
    }
    // note: adj goes to F_ADJ (fix of the store target above would double traffic;
    // store directly to F_ADJ instead)
    __syncthreads();
#pragma unroll
    for (int i = 0; i < 16; ++i) {             // move to F_ADJ (same layout)
        int idx = i * 256 + tid;
        int row = idx >> 5, c4 = idx & 31;
        *(float4*)&smf[F_ADJ + row * RL + c4 * 4] = *(float4*)&smf[F_ACT + row * RL + c4 * 4];
    }
    {                                          // W_h[0]^T -> WT (cvt), prefetch-identical map
        int cb = lane & 7;
        int u0 = warp * 16 + ((lane >> 3) << 2);
#pragma unroll
        for (int kk = 0; kk < 16; ++kk) {
            int c = 8 * kk + cb;
            float4 v = *(const float4*)(W_h + c * 128 + u0);
            smf[F_WT + (u0 + 0) * RL + c] = tf32r(v.x);
            smf[F_WT + (u0 + 1) * RL + c] = tf32r(v.y);
            smf[F_WT + (u0 + 2) * RL + c] = tf32r(v.z);
            smf[F_WT + (u0 + 3) * RL + c] = tf32r(v.w);
        }
    }
    if (tid < 128) {                           // x0 -> X0 (cvt)
        int p = tid;
        float4 f0 = *(const float4*)(feat + ((size_t)b * 128 + p) * 8);
        float4 f1 = *(const float4*)(feat + ((size_t)b * 128 + p) * 8 + 4);
        int pg = pdg[(size_t)b * 128 + p];
        float4 e0 = *(const float4*)(emb + pg * 8);
        float4 e1 = *(const float4*)(emb + pg * 8 + 4);
        float vv[16] = {f0.x,f0.y,f0.z,f0.w, f1.x,f1.y,f1.z,f1.w,
                        e0.x,e0.y,e0.z,e0.w, e1.x,e1.y,e1.z,e1.w};
#pragma unroll
        for (int j = 0; j < 16; ++j) smf[F_X0 + p * 16 + j] = tf32r(vv[j]);
    }
#pragma unroll
    for (int i = 0; i < 2; ++i) {              // W_in^T -> WINT (cvt)
        int idx = i * 256 + tid;
        int c = idx >> 5, u0 = (idx & 31) * 4;
        float4 wv = *(const float4*)(W_in + idx * 4);
        smf[F_WINT + (u0 + 0) * 24 + c] = tf32r(wv.x);
        smf[F_WINT + (u0 + 1) * 24 + c] = tf32r(wv.y);
        smf[F_WINT + (u0 + 2) * 24 + c] = tf32r(wv.z);
        smf[F_WINT + (u0 + 3) * 24 + c] = tf32r(wv.w);
    }
    if (tid < 192) {                           // b_h
        *(float4*)&smf[F_BIA + tid * 4] = *(const float4*)(b_h + tid * 4);
    }
    if (tid < 32) {                            // b_in
        *(float4*)&smf[F_BIN + tid * 4] = *(const float4*)(b_in + tid * 4);
    } else if (tid < 64) {                     // mask
        int q = tid - 32;
        *(float4*)&smf[F_MSK + q * 4] = *(const float4*)(mask + (size_t)b * 128 + q * 4);
    } else if (tid < 96) {                     // W_out
        int q = tid - 64;
        *(float4*)&smf[F_WO + q * 4] = *(const float4*)(W_out + q * 4);
    } else if (tid == 96) {
        smf[F_BOUT] = b_out[0];
    }
    __syncthreads();

    if (warp == 0) {                           // denom
        float s = smf[F_MSK + lane] + smf[F_MSK + lane + 32]
                + smf[F_MSK + lane + 64] + smf[F_MSK + lane + 96];
#pragma unroll
        for (int o = 16; o; o >>= 1) s += __shfl_down_sync(0xffffffffu, s, o);
        if (lane == 0) smf[F_RED + 7] = fmaxf(s, 1.0f);
    }

    float acc[4][4][4];

    // ================= input GEMM: X = x0 @ W_in + b_in (K=16) =================
    zero_acc(acc);
    {
        uint32_t aA = SB + F_X0 * 4
                    + (uint32_t)((m0 + aRow) * 16) * 4 + (uint32_t)aCol16 * 16;
        uint32_t aB = SB + F_WINT * 4
                    + (uint32_t)((n0 + aRow) * 24) * 4 + (uint32_t)aCol16 * 16;
        const uint32_t MSA = 16u * 16u * 4u;   // 16 rows of X0 (stride 16 floats)
        const uint32_t MSB = 16u * 24u * 4u;
#pragma unroll
        for (int k = 0; k < 2; ++k) {
            uint32_t A4[4][4], B4[2][4];
#pragma unroll
            for (int mt = 0; mt < 4; ++mt)
                ldsm4(aA + mt * MSA + k * 32u, A4[mt][0], A4[mt][1], A4[mt][2], A4[mt][3]);
#pragma unroll
            for (int nb = 0; nb < 2; ++nb)
                ldsm4(aB + nb * MSB + k * 32u, B4[nb][0], B4[nb][1], B4[nb][2], B4[nb][3]);
#pragma unroll
            for (int mt = 0; mt < 4; ++mt)
#pragma unroll
                for (int nt = 0; nt < 4; ++nt)
                    mma8(acc[mt][nt], A4[mt][0], A4[mt][1], A4[mt][2], A4[mt][3],
                         B4[nt >> 1][nt & 1], B4[nt >> 1][(nt & 1) + 2]);
        }
    }
    // epilogue: + b_in, cvt, store X row-major into ACT
#pragma unroll
    for (int mt = 0; mt < 4; ++mt)
#pragma unroll
        for (int nt = 0; nt < 4; ++nt) {
            int p0 = m0 + mt * 16 + er;
            int u0 = n0 + nt * 8 + ec;
            float bi0 = smf[F_BIN + u0], bi1 = smf[F_BIN + u0 + 1];
            *(float2*)&smf[F_ACT + p0 * RL + u0] =
                make_float2(tf32r(acc[mt][nt][0] + bi0), tf32r(acc[mt][nt][1] + bi1));
            *(float2*)&smf[F_ACT + (p0 + 8) * RL + u0] =
                make_float2(tf32r(acc[mt][nt][2] + bi0), tf32r(acc[mt][nt][3] + bi1));
        }
    __syncthreads();

    // ================= hidden layers =================
    const uint32_t actB = SB + F_ACT * 4;
    const uint32_t adjB = SB + F_ADJ * 4;
    const uint32_t wtB  = SB + F_WT * 4;

#pragma unroll 1
    for (int l = 0; l < NHID; ++l) {
        // GEMM1: Y[p][u] = X @ W_h[l]
        zero_acc(acc);
        gemm128<false>(actB + (uint32_t)(m0 * RL) * 4 + fragOff,
                       wtB  + (uint32_t)(n0 * RL) * 4 + fragOff,
                       acc, nullptr, smf, warp, lane);
        __syncthreads();
        // epi1: relu(+bias), cvt, store Y^T into ACT
#pragma unroll
        for (int nt = 0; nt < 4; ++nt) {
            int u0 = n0 + nt * 8 + ec;
            float bi0 = smf[F_BIA + l * 128 + u0];
            float bi1 = smf[F_BIA + l * 128 + u0 + 1];
#pragma unroll
            for (int mt = 0; mt < 4; ++mt) {
                int p0 = m0 + mt * 16 + er;
                smf[F_ACT + u0 * RL + p0]           = tf32r(fmaxf(acc[mt][nt][0] + bi0, 0.0f));
                smf[F_ACT + (u0 + 1) * RL + p0]     = tf32r(fmaxf(acc[mt][nt][1] + bi1, 0.0f));
                smf[F_ACT + u0 * RL + p0 + 8]       = tf32r(fmaxf(acc[mt][nt][2] + bi0, 0.0f));
                smf[F_ACT + (u0 + 1) * RL + p0 + 8] = tf32r(fmaxf(acc[mt][nt][3] + bi1, 0.0f));
            }
        }
        __syncthreads();

        // GEMM2: X'[p][u] = adj @ Y  (+ prefetch W_h[l+1] into WT)
        zero_acc(acc);
        if (l + 1 < NHID)
            gemm128<true>(adjB + (uint32_t)(m0 * RL) * 4 + fragOff,
                          actB + (uint32_t)(n0 * RL) * 4 + fragOff,
                          acc, W_h + (size_t)(l + 1) * 16384, smf, warp, lane);
        else
            gemm128<false>(adjB + (uint32_t)(m0 * RL) * 4 + fragOff,
                           actB + (uint32_t)(n0 * RL) * 4 + fragOff,
                           acc, nullptr, smf, warp, lane);
        __syncthreads();
        // epi2: store X' row-major into ACT (cvt unless last layer)
        const bool last = (l == NHID - 1);
#pragma unroll
        for (int mt = 0; mt < 4; ++mt)
#pragma unroll
            for (int nt = 0; nt < 4; ++nt) {
                int p0 = m0 + mt * 16 + er;
                int u0 = n0 + nt * 8 + ec;
                float v0 = acc[mt][nt][0], v1 = acc[mt][nt][1];
                float v2 = acc[mt][nt][2], v3 = acc[mt][nt][3];
                if (!last) { v0 = tf32r(v0); v1 = tf32r(v1); v2 = tf32r(v2); v3 = tf32r(v3); }
                *(float2*)&smf[F_ACT + p0 * RL + u0]       = make_float2(v0, v1);
                *(float2*)&smf[F_ACT + (p0 + 8) * RL + u0] = make_float2(v2, v3);
            }
        __syncthreads();
    }

    // ================= masked mean pool + output projection =================
    {
        int u = tid & 127;
        int h = tid >> 7;                      // 0..1
        float s = 0.0f;
#pragma unroll 8
        for (int i = 0; i < 64; ++i) {
            int p = h * 64 + i;
            s += smf[F_ACT + p * RL + u] * smf[F_MSK + p];
        }
        smf[F_PART + h * 128 + u] = s;
    }
    __syncthreads();
    if (tid < 128) {
        float pooled = (smf[F_PART + tid] + smf[F_PART + 128 + tid]) / smf[F_RED + 7];
        float v = pooled * smf[F_WO + tid];
#pragma unroll
        for (int o = 16; o; o >>= 1) v += __shfl_down_sync(0xffffffffu, v, o);
        if ((tid & 31) == 0) smf[F_RED + (tid >> 5)] = v;
    }
    __syncthreads();
    if (tid == 0)
        out[b] = smf[F_RED + 0] + smf[F_RED + 1] + smf[F_RED + 2] + smf[F_RED + 3]
               + smf[F_BOUT];
}

extern "C" void kernel_launch(void* const* d_in, const int* in_sizes, int n_in,
                              void* d_out, int out_size)
{
    const int*   pdg   = (const int*)  d_in[0];
    const float* feat  = (const float*)d_in[1];
    const float* adjp  = (const float*)d_in[2];
    const float* maskp = (const float*)d_in[3];
    const float* emb   = (const float*)d_in[4];
    const float* W_in  = (const float*)d_in[5];
    const float* b_in  = (const float*)d_in[6];
    const float* W_h   = (const float*)d_in[7];
    const float* b_h   = (const float*)d_in[8];
    const float* W_out = (const float*)d_in[9];
    const float* b_out = (const float*)d_in[10];
    float* out = (float*)d_out;

    const int B = in_sizes[0] / 128;

    cudaFuncSetAttribute(gcn_mma_kernel,
                         cudaFuncAttributeMaxDynamicSharedMemorySize, SMEM_BYTES);
    gcn_mma_kernel<<<B, NTH, SMEM_BYTES>>>(
        pdg, feat, adjp, maskp, emb, W_in, b_in, W_h, b_h, W_out, b_out, out);
}

// round 10
// speedup vs baseline: 1.0166x; 1.0166x over previous
#include <cuda_runtime.h>
#include <cstdint>

#define RL   132
#define NTH  256
#define NHID 6

// float offsets in dynamic smem
#define F_ADJ  0                 // 128*132 adj row-major (A of GEMM2)
#define F_ACT  16896             // 128*132 X / Y^T / X' multiplexed
#define F_WT   33792             // 128*132 W^T[u][c] (A of GEMM1)
#define F_X0   50688             // 128*16 input features (A of input GEMM)
#define F_WINT 52736             // 128*24 W_in^T (B of input GEMM)
#define F_BIN  55808             // 128
#define F_BIA  55936             // 768
#define F_MSK  56704             // 128
#define F_WO   56832             // 128
#define F_PART 56960             // 512 (only 256 used)
#define F_RED  57472             // 8 (RED[7] = denom)
#define F_BOUT 57480
#define SMEM_FLOATS 57488
#define SMEM_BYTES  (SMEM_FLOATS * 4)

__device__ __forceinline__ uint32_t smem_u32(const void* p) {
    uint32_t a;
    asm("{ .reg .u64 t; cvta.to.shared.u64 t, %1; cvt.u32.u64 %0, t; }" : "=r"(a) : "l"(p));
    return a;
}

__device__ __forceinline__ float tf32r(float x) {
    float y;
    asm("cvt.rna.tf32.f32 %0, %1;" : "=f"(y) : "f"(x));
    return y;
}

__device__ __forceinline__ void ldsm4(uint32_t addr, uint32_t& r0, uint32_t& r1,
                                      uint32_t& r2, uint32_t& r3) {
    asm volatile("ldmatrix.sync.aligned.m8n8.x4.shared.b16 {%0,%1,%2,%3}, [%4];"
                 : "=r"(r0), "=r"(r1), "=r"(r2), "=r"(r3) : "r"(addr));
}

__device__ __forceinline__ void mma8(float* d,
                                     uint32_t a0, uint32_t a1, uint32_t a2, uint32_t a3,
                                     uint32_t b0, uint32_t b1) {
    asm volatile("mma.sync.aligned.m16n8k8.row.col.f32.tf32.tf32.f32 "
                 "{%0,%1,%2,%3}, {%4,%5,%6,%7}, {%8,%9}, {%0,%1,%2,%3};"
                 : "+f"(d[0]), "+f"(d[1]), "+f"(d[2]), "+f"(d[3])
                 : "r"(a0), "r"(a1), "r"(a2), "r"(a3), "r"(b0), "r"(b1));
}

__device__ __forceinline__ void zero_acc(float (&acc)[4][4][4]) {
#pragma unroll
    for (int i = 0; i < 4; ++i)
#pragma unroll
        for (int j = 0; j < 4; ++j)
#pragma unroll
            for (int q = 0; q < 4; ++q) acc[i][j][q] = 0.0f;
}

// 128x128x128 GEMM, 8 warps, 64x32 warp tiles.
// A row-major [m][k] stride RL at aA, B^T row-major [n][k] stride RL at aB.
// Explicit k double-buffer pipeline.
// PREF: stage W[l+1]^T (global row-major [c][u]) into F_WT, spread over k-steps.
template<bool PREF>
__device__ __forceinline__ void gemm128(uint32_t aA, uint32_t aB,
                                        float (&acc)[4][4][4],
                                        const float* __restrict__ wg,
                                        float* __restrict__ smf,
                                        int warp, int lane) {
    const uint32_t MSTEP = 16u * RL * 4u;
    uint32_t A[2][4][4];
    uint32_t B[2][2][4];
    float4 ring[4];
    int cbase = 0, ubase = 0;
    if (PREF) {
        cbase = lane & 7;                       // c = 8k + cbase
        ubase = warp * 16 + ((lane >> 3) << 2); // u0 (4 consecutive u per lane)
#pragma unroll
        for (int r = 0; r < 4; ++r)
            ring[r] = *(const float4*)(wg + (8 * r + cbase) * 128 + ubase);
    }
    // k = 0 fragments
#pragma unroll
    for (int mt = 0; mt < 4; ++mt)
        ldsm4(aA + mt * MSTEP, A[0][mt][0], A[0][mt][1], A[0][mt][2], A[0][mt][3]);
#pragma unroll
    for (int nb = 0; nb < 2; ++nb)
        ldsm4(aB + nb * MSTEP, B[0][nb][0], B[0][nb][1], B[0][nb][2], B[0][nb][3]);

#pragma unroll
    for (int k = 0; k < 16; ++k) {
        const int cur = k & 1, nxt = cur ^ 1;
        if (k < 15) {
#pragma unroll
            for (int mt = 0; mt < 4; ++mt)
                ldsm4(aA + mt * MSTEP + (uint32_t)(k + 1) * 32u,
                      A[nxt][mt][0], A[nxt][mt][1], A[nxt][mt][2], A[nxt][mt][3]);
#pragma unroll
            for (int nb = 0; nb < 2; ++nb)
                ldsm4(aB + nb * MSTEP + (uint32_t)(k + 1) * 32u,
                      B[nxt][nb][0], B[nxt][nb][1], B[nxt][nb][2], B[nxt][nb][3]);
        }
#pragma unroll
        for (int mt = 0; mt < 4; ++mt)
#pragma unroll
            for (int nt = 0; nt < 4; ++nt)
                mma8(acc[mt][nt],
                     A[cur][mt][0], A[cur][mt][1], A[cur][mt][2], A[cur][mt][3],
                     B[cur][nt >> 1][nt & 1], B[cur][nt >> 1][(nt & 1) + 2]);
        if (PREF && k >= 1) {
            const int kk = k - 1;
            const int c = 8 * kk + cbase;
            float4 v = ring[kk & 3];
            smf[F_WT + (ubase + 0) * RL + c] = tf32r(v.x);
            smf[F_WT + (ubase + 1) * RL + c] = tf32r(v.y);
            smf[F_WT + (ubase + 2) * RL + c] = tf32r(v.z);
            smf[F_WT + (ubase + 3) * RL + c] = tf32r(v.w);
            if (kk + 4 < 16)
                ring[kk & 3] = *(const float4*)(wg + (8 * (kk + 4) + cbase) * 128 + ubase);
        }
    }
    if (PREF) {
        const int c = 8 * 15 + cbase;
        float4 v = ring[15 & 3];
        smf[F_WT + (ubase + 0) * RL + c] = tf32r(v.x);
        smf[F_WT + (ubase + 1) * RL + c] = tf32r(v.y);
        smf[F_WT + (ubase + 2) * RL + c] = tf32r(v.z);
        smf[F_WT + (ubase + 3) * RL + c] = tf32r(v.w);
    }
}

__global__ __launch_bounds__(NTH, 1)
void gcn_mma_kernel(const int* __restrict__ pdg,
                    const float* __restrict__ feat,
                    const float* __restrict__ adj,
                    const float* __restrict__ mask,
                    const float* __restrict__ emb,
                    const float* __restrict__ W_in,
                    const float* __restrict__ b_in,
                    const float* __restrict__ W_h,
                    const float* __restrict__ b_h,
                    const float* __restrict__ W_out,
                    const float* __restrict__ b_out,
                    float* __restrict__ out)
{
    extern __shared__ float smf[];
    const uint32_t SB = smem_u32(smf);

    const int b    = blockIdx.x;
    const int tid  = threadIdx.x;
    const int lane = tid & 31;
    const int warp = tid >> 5;          // 0..7

    // 8 warps: 2 (m) x 4 (n), warp tile 64x32
    const int m0 = (warp >> 2) * 64;
    const int n0 = (warp & 3) * 32;

    // ldmatrix per-thread segment pattern
    const int aRow   = (lane & 7) + ((lane >> 3) & 1) * 8;
    const int aCol16 = lane >> 4;
    const uint32_t fragOff = (uint32_t)(aRow * RL) * 4 + (uint32_t)aCol16 * 16;

    // epilogue pattern
    const int er = lane >> 2;
    const int ec = (lane & 3) * 2;

    const float* adjb = adj + (size_t)b * 16384;

    // ================= staging =================
#pragma unroll
    for (int i = 0; i < 16; ++i) {             // adj -> ADJ (cvt), direct
        int idx = i * 256 + tid;
        int row = idx >> 5, c4 = idx & 31;
        float4 v = *(const float4*)(adjb + row * 128 + c4 * 4);
        float4 w = make_float4(tf32r(v.x), tf32r(v.y), tf32r(v.z), tf32r(v.w));
        *(float4*)&smf[F_ADJ + row * RL + c4 * 4] = w;
    }
    {                                          // W_h[0]^T -> WT (cvt), prefetch-identical map
        int cb = lane & 7;
        int u0 = warp * 16 + ((lane >> 3) << 2);
#pragma unroll
        for (int kk = 0; kk < 16; ++kk) {
            int c = 8 * kk + cb;
            float4 v = *(const float4*)(W_h + c * 128 + u0);
            smf[F_WT + (u0 + 0) * RL + c] = tf32r(v.x);
            smf[F_WT + (u0 + 1) * RL + c] = tf32r(v.y);
            smf[F_WT + (u0 + 2) * RL + c] = tf32r(v.z);
            smf[F_WT + (u0 + 3) * RL + c] = tf32r(v.w);
        }
    }
    if (tid < 128) {                           // x0 -> X0 (cvt)
        int p = tid;
        float4 f0 = *(const float4*)(feat + ((size_t)b * 128 + p) * 8);
        float4 f1 = *(const float4*)(feat + ((size_t)b * 128 + p) * 8 + 4);
        int pg = pdg[(size_t)b * 128 + p];
        float4 e0 = *(const float4*)(emb + pg * 8);
        float4 e1 = *(const float4*)(emb + pg * 8 + 4);
        float vv[16] = {f0.x,f0.y,f0.z,f0.w, f1.x,f1.y,f1.z,f1.w,
                        e0.x,e0.y,e0.z,e0.w, e1.x,e1.y,e1.z,e1.w};
#pragma unroll
        for (int j = 0; j < 16; ++j) smf[F_X0 + p * 16 + j] = tf32r(vv[j]);
    }
#pragma unroll
    for (int i = 0; i < 2; ++i) {              // W_in^T -> WINT (cvt)
        int idx = i * 256 + tid;
        int c = idx >> 5, u0 = (idx & 31) * 4;
        float4 wv = *(const float4*)(W_in + idx * 4);
        smf[F_WINT + (u0 + 0) * 24 + c] = tf32r(wv.x);
        smf[F_WINT + (u0 + 1) * 24 + c] = tf32r(wv.y);
        smf[F_WINT + (u0 + 2) * 24 + c] = tf32r(wv.z);
        smf[F_WINT + (u0 + 3) * 24 + c] = tf32r(wv.w);
    }
    if (tid < 192) {                           // b_h
        *(float4*)&smf[F_BIA + tid * 4] = *(const float4*)(b_h + tid * 4);
    }
    if (tid < 32) {                            // b_in
        *(float4*)&smf[F_BIN + tid * 4] = *(const float4*)(b_in + tid * 4);
    } else if (tid < 64) {                     // mask
        int q = tid - 32;
        *(float4*)&smf[F_MSK + q * 4] = *(const float4*)(mask + (size_t)b * 128 + q * 4);
    } else if (tid < 96) {                     // W_out
        int q = tid - 64;
        *(float4*)&smf[F_WO + q * 4] = *(const float4*)(W_out + q * 4);
    } else if (tid == 96) {
        smf[F_BOUT] = b_out[0];
    }
    __syncthreads();

    if (warp == 0) {                           // denom
        float s = smf[F_MSK + lane] + smf[F_MSK + lane + 32]
                + smf[F_MSK + lane + 64] + smf[F_MSK + lane + 96];
#pragma unroll
        for (int o = 16; o; o >>= 1) s += __shfl_down_sync(0xffffffffu, s, o);
        if (lane == 0) smf[F_RED + 7] = fmaxf(s, 1.0f);
    }

    float acc[4][4][4];

    // ================= input GEMM: X = x0 @ W_in + b_in (K=16) =================
    // m = p (particles), n = u; output X row-major [p][u].
    zero_acc(acc);
    {
        uint32_t aA = SB + F_X0 * 4
                    + (uint32_t)((m0 + aRow) * 16) * 4 + (uint32_t)aCol16 * 16;
        uint32_t aB = SB + F_WINT * 4
                    + (uint32_t)((n0 + aRow) * 24) * 4 + (uint32_t)aCol16 * 16;
        const uint32_t MSA = 16u * 16u * 4u;
        const uint32_t MSB = 16u * 24u * 4u;
#pragma unroll
        for (int k = 0; k < 2; ++k) {
            uint32_t A4[4][4], B4[2][4];
#pragma unroll
            for (int mt = 0; mt < 4; ++mt)
                ldsm4(aA + mt * MSA + k * 32u, A4[mt][0], A4[mt][1], A4[mt][2], A4[mt][3]);
#pragma unroll
            for (int nb = 0; nb < 2; ++nb)
                ldsm4(aB + nb * MSB + k * 32u, B4[nb][0], B4[nb][1], B4[nb][2], B4[nb][3]);
#pragma unroll
            for (int mt = 0; mt < 4; ++mt)
#pragma unroll
                for (int nt = 0; nt < 4; ++nt)
                    mma8(acc[mt][nt], A4[mt][0], A4[mt][1], A4[mt][2], A4[mt][3],
                         B4[nt >> 1][nt & 1], B4[nt >> 1][(nt & 1) + 2]);
        }
    }
    // epilogue: + b_in, cvt, store X row-major into ACT
#pragma unroll
    for (int mt = 0; mt < 4; ++mt)
#pragma unroll
        for (int nt = 0; nt < 4; ++nt) {
            int p0 = m0 + mt * 16 + er;
            int u0 = n0 + nt * 8 + ec;
            float bi0 = smf[F_BIN + u0], bi1 = smf[F_BIN + u0 + 1];
            *(float2*)&smf[F_ACT + p0 * RL + u0] =
                make_float2(tf32r(acc[mt][nt][0] + bi0), tf32r(acc[mt][nt][1] + bi1));
            *(float2*)&smf[F_ACT + (p0 + 8) * RL + u0] =
                make_float2(tf32r(acc[mt][nt][2] + bi0), tf32r(acc[mt][nt][3] + bi1));
        }
    __syncthreads();

    // ================= hidden layers =================
    const uint32_t actB = SB + F_ACT * 4;
    const uint32_t adjB = SB + F_ADJ * 4;
    const uint32_t wtB  = SB + F_WT * 4;

#pragma unroll 1
    for (int l = 0; l < NHID; ++l) {
        // GEMM1 (flipped): Y^T[u][p] = W^T[u][:] @ X^T[:][p]
        //   A = WT rows u (m-dim), B^T = X row-major rows p (n-dim).
        zero_acc(acc);
        gemm128<false>(wtB  + (uint32_t)(m0 * RL) * 4 + fragOff,
                       actB + (uint32_t)(n0 * RL) * 4 + fragOff,
                       acc, nullptr, smf, warp, lane);
        __syncthreads();
        // epi1: relu(+bias over u), cvt, store Y^T ROW-MAJOR (float2 along p)
#pragma unroll
        for (int mt = 0; mt < 4; ++mt) {
            int u0 = m0 + mt * 16 + er;
            float bi  = smf[F_BIA + l * 128 + u0];
            float bi8 = smf[F_BIA + l * 128 + u0 + 8];
#pragma unroll
            for (int nt = 0; nt < 4; ++nt) {
                int p0 = n0 + nt * 8 + ec;
                *(float2*)&smf[F_ACT + u0 * RL + p0] =
                    make_float2(tf32r(fmaxf(acc[mt][nt][0] + bi, 0.0f)),
                                tf32r(fmaxf(acc[mt][nt][1] + bi, 0.0f)));
                *(float2*)&smf[F_ACT + (u0 + 8) * RL + p0] =
                    make_float2(tf32r(fmaxf(acc[mt][nt][2] + bi8, 0.0f)),
                                tf32r(fmaxf(acc[mt][nt][3] + bi8, 0.0f)));
            }
        }
        __syncthreads();

        // GEMM2: X'[p][u] = adj @ Y : A = ADJ rows p, B^T = Y^T rows u.
        //   (+ prefetch W_h[l+1] into WT)
        zero_acc(acc);
        if (l + 1 < NHID)
            gemm128<true>(adjB + (uint32_t)(m0 * RL) * 4 + fragOff,
                          actB + (uint32_t)(n0 * RL) * 4 + fragOff,
                          acc, W_h + (size_t)(l + 1) * 16384, smf, warp, lane);
        else
            gemm128<false>(adjB + (uint32_t)(m0 * RL) * 4 + fragOff,
                           actB + (uint32_t)(n0 * RL) * 4 + fragOff,
                           acc, nullptr, smf, warp, lane);
        __syncthreads();
        // epi2: store X' row-major into ACT (cvt unless last layer)
        const bool last = (l == NHID - 1);
#pragma unroll
        for (int mt = 0; mt < 4; ++mt)
#pragma unroll
            for (int nt = 0; nt < 4; ++nt) {
                int p0 = m0 + mt * 16 + er;
                int u0 = n0 + nt * 8 + ec;
                float v0 = acc[mt][nt][0], v1 = acc[mt][nt][1];
                float v2 = acc[mt][nt][2], v3 = acc[mt][nt][3];
                if (!last) { v0 = tf32r(v0); v1 = tf32r(v1); v2 = tf32r(v2); v3 = tf32r(v3); }
                *(float2*)&smf[F_ACT + p0 * RL + u0]       = make_float2(v0, v1);
                *(float2*)&smf[F_ACT + (p0 + 8) * RL + u0] = make_float2(v2, v3);
            }
        __syncthreads();
    }

    // ================= masked mean pool + output projection =================
    {
        int u = tid & 127;
        int h = tid >> 7;                      // 0..1
        float s = 0.0f;
#pragma unroll 8
        for (int i = 0; i < 64; ++i) {
            int p = h * 64 + i;
            s += smf[F_ACT + p * RL + u] * smf[F_MSK + p];
        }
        smf[F_PART + h * 128 + u] = s;
    }
    __syncthreads();
    if (tid < 128) {
        float pooled = (smf[F_PART + tid] + smf[F_PART + 128 + tid]) / smf[F_RED + 7];
        float v = pooled * smf[F_WO + tid];
#pragma unroll
        for (int o = 16; o; o >>= 1) v += __shfl_down_sync(0xffffffffu, v, o);
        if ((tid & 31) == 0) smf[F_RED + (tid >> 5)] = v;
    }
    __syncthreads();
    if (tid == 0)
        out[b] = smf[F_RED + 0] + smf[F_RED + 1] + smf[F_RED + 2] + smf[F_RED + 3]
               + smf[F_BOUT];
}

extern "C" void kernel_launch(void* const* d_in, const int* in_sizes, int n_in,
                              void* d_out, int out_size)
{
    const int*   pdg   = (const int*)  d_in[0];
    const float* feat  = (const float*)d_in[1];
    const float* adjp  = (const float*)d_in[2];
    const float* maskp = (const float*)d_in[3];
    const float* emb   = (const float*)d_in[4];
    const float* W_in  = (const float*)d_in[5];
    const float* b_in  = (const float*)d_in[6];
    const float* W_h   = (const float*)d_in[7];
    const float* b_h   = (const float*)d_in[8];
    const float* W_out = (const float*)d_in[9];
    const float* b_out = (const float*)d_in[10];
    float* out = (float*)d_out;

    const int B = in_sizes[0] / 128;

    cudaFuncSetAttribute(gcn_mma_kernel,
                         cudaFuncAttributeMaxDynamicSharedMemorySize, SMEM_BYTES);
    gcn_mma_kernel<<<B, NTH, SMEM_BYTES>>>(
        pdg, feat, adjp, maskp, emb, W_in, b_in, W_h, b_h, W_out, b_out, out);
}